// round 2
// baseline (speedup 1.0000x reference)
#include <cuda_runtime.h>
#include <math.h>

#define N_G    4096
#define BATCH  2
#define H_IMG  128
#define W_IMG  128
#define NSPLIT 8
#define TY     8
#define CHUNK  64
#define NPB    (N_G / NSPLIT)   // 512 gaussians per split
#define NYT    (H_IMG / TY)     // 16 y-tiles

typedef unsigned long long u64;

// Scratch (device globals; no allocation allowed)
__device__ float  g_Ex[BATCH * N_G * W_IMG];               // 4 MB
__device__ float  g_Ey[BATCH * N_G * H_IMG];               // 4 MB
__device__ float4 g_P [BATCH * N_G];                       // per (b,n): px, py, inv2v
__device__ float4 g_G [N_G];                               // (op*r, op*g, op*b, op)
__device__ float4 g_part[NSPLIT * BATCH * H_IMG * W_IMG];  // 4 MB partial sums

// ---- f32x2 packed helpers (Blackwell FFMA2 path, PTX-only) -----------------
__device__ __forceinline__ u64 pk2(float a, float b) {
    u64 r; asm("mov.b64 %0, {%1,%2};" : "=l"(r) : "f"(a), "f"(b)); return r;
}
__device__ __forceinline__ void upk2(u64 v, float& a, float& b) {
    asm("mov.b64 {%0,%1}, %2;" : "=f"(a), "=f"(b) : "l"(v));
}
__device__ __forceinline__ u64 mul2(u64 a, u64 b) {
    u64 r; asm("mul.rn.f32x2 %0, %1, %2;" : "=l"(r) : "l"(a), "l"(b)); return r;
}
__device__ __forceinline__ u64 fma2(u64 a, u64 b, u64 c) {
    u64 r; asm("fma.rn.f32x2 %0, %1, %2, %3;" : "=l"(r) : "l"(a), "l"(b), "l"(c)); return r;
}

// ---------------------------------------------------------------------------
// Kernel P1: per (b,n) projection params + per-n color vector. 8192 threads.
// ---------------------------------------------------------------------------
__global__ __launch_bounds__(256) void param_kernel(
    const float* __restrict__ pos, const float* __restrict__ col,
    const float* __restrict__ opa, const float* __restrict__ sca,
    const float* __restrict__ qv,  const float* __restrict__ tv)
{
    int idx = blockIdx.x * blockDim.x + threadIdx.x;
    if (idx >= BATCH * N_G) return;
    int b = idx / N_G;
    int n = idx - b * N_G;

    float qw = qv[b*4+0], qx = qv[b*4+1], qy = qv[b*4+2], qz = qv[b*4+3];
    float inv = rsqrtf(qw*qw + qx*qx + qy*qy + qz*qz);
    qw *= inv; qx *= inv; qy *= inv; qz *= inv;

    float r00 = 1.f - 2.f*(qy*qy + qz*qz), r01 = 2.f*(qx*qy - qz*qw), r02 = 2.f*(qx*qz + qy*qw);
    float r10 = 2.f*(qx*qy + qz*qw), r11 = 1.f - 2.f*(qx*qx + qz*qz), r12 = 2.f*(qy*qz - qx*qw);
    float r20 = 2.f*(qx*qz - qy*qw), r21 = 2.f*(qy*qz + qx*qw), r22 = 1.f - 2.f*(qx*qx + qy*qy);

    float p0 = pos[n*3+0], p1 = pos[n*3+1], p2 = pos[n*3+2];
    float cx = r00*p0 + r01*p1 + r02*p2 + tv[b*3+0];
    float cy = r10*p0 + r11*p1 + r12*p2 + tv[b*3+1];
    float cz = r20*p0 + r21*p1 + r22*p2 + tv[b*3+2];

    float invz = 1.0f / cz;
    float px = cx * invz * 500.0f + 64.0f;
    float py = cy * invz * 500.0f + 64.0f;
    float s  = sca[n];
    g_P[idx] = make_float4(px, py, 0.5f / (s*s), 0.f);

    if (b == 0) {
        float o = opa[n];
        g_G[n] = make_float4(o*col[n*3+0], o*col[n*3+1], o*col[n*3+2], o);
    }
}

// ---------------------------------------------------------------------------
// Kernel P2: fill Ex/Ey. One warp per (b,n) row: broadcast param load,
// each thread writes float4 of Ex and float4 of Ey (8 __expf each).
// ---------------------------------------------------------------------------
__global__ __launch_bounds__(256) void fill_kernel()
{
    int idx = blockIdx.x * blockDim.x + threadIdx.x;   // 0 .. 256K-1
    int r   = idx >> 5;          // (b*N_G + n), same for whole warp
    int x0  = (idx & 31) * 4;

    float4 P = g_P[r];
    float4 ex, ey;
    float f0 = (float)x0;
    {
        float d0 = f0     - P.x, d1 = f0+1.f - P.x, d2 = f0+2.f - P.x, d3 = f0+3.f - P.x;
        ex.x = __expf(-d0*d0*P.z); ex.y = __expf(-d1*d1*P.z);
        ex.z = __expf(-d2*d2*P.z); ex.w = __expf(-d3*d3*P.z);
    }
    {
        float d0 = f0     - P.y, d1 = f0+1.f - P.y, d2 = f0+2.f - P.y, d3 = f0+3.f - P.y;
        ey.x = __expf(-d0*d0*P.z); ey.y = __expf(-d1*d1*P.z);
        ey.z = __expf(-d2*d2*P.z); ey.w = __expf(-d3*d3*P.z);
    }
    *(float4*)(g_Ex + (size_t)r * W_IMG + x0) = ex;
    *(float4*)(g_Ey + (size_t)r * H_IMG + x0) = ey;
}

// ---------------------------------------------------------------------------
// Kernel 2: main contraction with packed f32x2 FMAs.
// Block = (batch, y-tile of 8 rows, n-split). 128 threads, thread = column x.
// Accumulators: 8 rows x {(r,g),(b,a)} packed -> 16 u64.
// ---------------------------------------------------------------------------
__global__ __launch_bounds__(128) void splat_kernel()
{
    int blk = blockIdx.x;
    int ns  = blk % NSPLIT;
    int yt  = (blk / NSPLIT) % NYT;
    int b   = blk / (NSPLIT * NYT);
    int x   = threadIdx.x;
    int y0  = yt * TY;
    int n0  = ns * NPB;

    __shared__ float  sEx[CHUNK * W_IMG];      // 32 KB
    __shared__ float4 sG [CHUNK];              // 1 KB  (read as 2x u64)
    __shared__ u64    sEy2[CHUNK * TY];        // 4 KB  (ey duplicated into both lanes)

    u64 accxy[TY], acczw[TY];
#pragma unroll
    for (int j = 0; j < TY; j++) { accxy[j] = 0ull; acczw[j] = 0ull; }

    const float* Exb = g_Ex + (size_t)(b*N_G + n0) * W_IMG;
    const float* Eyb = g_Ey + (size_t)(b*N_G + n0) * H_IMG + y0;

    for (int c0 = 0; c0 < NPB; c0 += CHUNK) {
        __syncthreads();
        // Ex chunk: CHUNK*W contiguous floats
        {
            const float4* src = (const float4*)(Exb + c0 * W_IMG);
            float4* dst = (float4*)sEx;
#pragma unroll
            for (int i = 0; i < (CHUNK * W_IMG / 4) / 128; i++)
                dst[i*128 + x] = src[i*128 + x];
        }
        // Ey chunk: thread x covers (nl = x>>1, half = x&1): 4 floats -> 4 dup'd u64
        {
            int nl   = x >> 1;
            int half = x & 1;
            float4 a = *(const float4*)(Eyb + (c0 + nl) * H_IMG + half * 4);
            u64* dst = &sEy2[nl * TY + half * 4];
            dst[0] = pk2(a.x, a.x);
            dst[1] = pk2(a.y, a.y);
            dst[2] = pk2(a.z, a.z);
            dst[3] = pk2(a.w, a.w);
        }
        if (x < CHUNK) sG[x] = g_G[n0 + c0 + x];
        __syncthreads();

#pragma unroll 4
        for (int nl = 0; nl < CHUNK; nl++) {
            float ex = sEx[nl * W_IMG + x];
            u64 exx  = pk2(ex, ex);
            ulonglong2 gv = *(const ulonglong2*)&sG[nl];   // (gx,gy) (gz,gw)
            u64 pxy = mul2(gv.x, exx);
            u64 pzw = mul2(gv.y, exx);
            const ulonglong2* eyp = (const ulonglong2*)&sEy2[nl * TY];
#pragma unroll
            for (int k = 0; k < TY/2; k++) {
                ulonglong2 e2 = eyp[k];
                accxy[2*k+0] = fma2(pxy, e2.x, accxy[2*k+0]);
                acczw[2*k+0] = fma2(pzw, e2.x, acczw[2*k+0]);
                accxy[2*k+1] = fma2(pxy, e2.y, accxy[2*k+1]);
                acczw[2*k+1] = fma2(pzw, e2.y, acczw[2*k+1]);
            }
        }
    }

    float4* pp = g_part + (size_t)(ns*BATCH + b) * H_IMG * W_IMG;
#pragma unroll
    for (int j = 0; j < TY; j++) {
        float4 v;
        upk2(accxy[j], v.x, v.y);
        upk2(acczw[j], v.z, v.w);
        pp[(y0 + j) * W_IMG + x] = v;
    }
}

// ---------------------------------------------------------------------------
// Kernel 3: reduce n-splits, normalize, write [B,3,H,W]
// ---------------------------------------------------------------------------
__global__ __launch_bounds__(256) void finalize_kernel(float* __restrict__ out)
{
    int idx = blockIdx.x * blockDim.x + threadIdx.x;
    if (idx >= BATCH * H_IMG * W_IMG) return;
    int b = idx / (H_IMG * W_IMG);
    int p = idx - b * (H_IMG * W_IMG);

    float sx = 0.f, sy = 0.f, sz = 0.f, sw = 0.f;
#pragma unroll
    for (int ns = 0; ns < NSPLIT; ns++) {
        float4 v = g_part[(size_t)(ns*BATCH + b) * H_IMG * W_IMG + p];
        sx += v.x; sy += v.y; sz += v.z; sw += v.w;
    }
    float invd = 1.0f / (sw + 1e-8f);
    size_t base = (size_t)b * 3 * H_IMG * W_IMG;
    out[base + 0*H_IMG*W_IMG + p] = sx * invd;
    out[base + 1*H_IMG*W_IMG + p] = sy * invd;
    out[base + 2*H_IMG*W_IMG + p] = sz * invd;
}

// ---------------------------------------------------------------------------
extern "C" void kernel_launch(void* const* d_in, const int* in_sizes, int n_in,
                              void* d_out, int out_size)
{
    const float* positions = (const float*)d_in[0];
    const float* colors    = (const float*)d_in[1];
    const float* opacities = (const float*)d_in[2];
    const float* scales    = (const float*)d_in[3];
    const float* qvec      = (const float*)d_in[4];
    const float* tvec      = (const float*)d_in[5];
    float* out = (float*)d_out;

    param_kernel<<<(BATCH * N_G + 255) / 256, 256>>>(positions, colors, opacities, scales, qvec, tvec);
    fill_kernel<<<(BATCH * N_G * W_IMG / 4) / 256, 256>>>();
    splat_kernel<<<BATCH * NYT * NSPLIT, 128>>>();
    finalize_kernel<<<(BATCH * H_IMG * W_IMG + 255) / 256, 256>>>(out);
}

// round 5
// speedup vs baseline: 1.5836x; 1.5836x over previous
#include <cuda_runtime.h>
#include <math.h>

#define N_G    4096
#define BATCH  2
#define H_IMG  128
#define W_IMG  128
#define NSPLIT 8
#define TY     8
#define CHUNK  64
#define NPB    (N_G / NSPLIT)   // 512 gaussians per split
#define NYT    (H_IMG / TY)     // 16 y-tiles

// Scratch (device globals; no allocation allowed)
__device__ float  g_Ex[BATCH * N_G * W_IMG];               // 4 MB
__device__ float  g_Ey[BATCH * N_G * H_IMG];               // 4 MB
__device__ float4 g_P [BATCH * N_G];                       // per (b,n): px, py, inv2v
__device__ float4 g_G [N_G];                               // (op*r, op*g, op*b, op)
__device__ float4 g_part[NSPLIT * BATCH * H_IMG * W_IMG];  // 4 MB partial sums

// ---------------------------------------------------------------------------
// Kernel P1: per (b,n) projection params + per-n color vector. 8192 threads.
// ---------------------------------------------------------------------------
__global__ __launch_bounds__(256) void param_kernel(
    const float* __restrict__ pos, const float* __restrict__ col,
    const float* __restrict__ opa, const float* __restrict__ sca,
    const float* __restrict__ qv,  const float* __restrict__ tv)
{
    int idx = blockIdx.x * blockDim.x + threadIdx.x;
    if (idx >= BATCH * N_G) return;
    int b = idx / N_G;
    int n = idx - b * N_G;

    float qw = qv[b*4+0], qx = qv[b*4+1], qy = qv[b*4+2], qz = qv[b*4+3];
    float inv = rsqrtf(qw*qw + qx*qx + qy*qy + qz*qz);
    qw *= inv; qx *= inv; qy *= inv; qz *= inv;

    float r00 = 1.f - 2.f*(qy*qy + qz*qz), r01 = 2.f*(qx*qy - qz*qw), r02 = 2.f*(qx*qz + qy*qw);
    float r10 = 2.f*(qx*qy + qz*qw), r11 = 1.f - 2.f*(qx*qx + qz*qz), r12 = 2.f*(qy*qz - qx*qw);
    float r20 = 2.f*(qx*qz - qy*qw), r21 = 2.f*(qy*qz + qx*qw), r22 = 1.f - 2.f*(qx*qx + qy*qy);

    float p0 = pos[n*3+0], p1 = pos[n*3+1], p2 = pos[n*3+2];
    float cx = r00*p0 + r01*p1 + r02*p2 + tv[b*3+0];
    float cy = r10*p0 + r11*p1 + r12*p2 + tv[b*3+1];
    float cz = r20*p0 + r21*p1 + r22*p2 + tv[b*3+2];

    float invz = 1.0f / cz;
    float px = cx * invz * 500.0f + 64.0f;
    float py = cy * invz * 500.0f + 64.0f;
    float s  = sca[n];
    g_P[idx] = make_float4(px, py, 0.5f / (s*s), 0.f);

    if (b == 0) {
        float o = opa[n];
        g_G[n] = make_float4(o*col[n*3+0], o*col[n*3+1], o*col[n*3+2], o);
    }
}

// ---------------------------------------------------------------------------
// Kernel P2: fill Ex/Ey. 32 threads per (b,n) row: broadcast param load,
// each thread writes float4 of Ex and float4 of Ey (8 __expf each).
// ---------------------------------------------------------------------------
__global__ __launch_bounds__(256) void fill_kernel()
{
    int idx = blockIdx.x * blockDim.x + threadIdx.x;   // 0 .. 256K-1
    int r   = idx >> 5;          // (b*N_G + n), same for whole warp
    int x0  = (idx & 31) * 4;

    float4 P = g_P[r];
    float4 ex, ey;
    float f0 = (float)x0;
    {
        float d0 = f0     - P.x, d1 = f0+1.f - P.x, d2 = f0+2.f - P.x, d3 = f0+3.f - P.x;
        ex.x = __expf(-d0*d0*P.z); ex.y = __expf(-d1*d1*P.z);
        ex.z = __expf(-d2*d2*P.z); ex.w = __expf(-d3*d3*P.z);
    }
    {
        float d0 = f0     - P.y, d1 = f0+1.f - P.y, d2 = f0+2.f - P.y, d3 = f0+3.f - P.y;
        ey.x = __expf(-d0*d0*P.z); ey.y = __expf(-d1*d1*P.z);
        ey.z = __expf(-d2*d2*P.z); ey.w = __expf(-d3*d3*P.z);
    }
    *(float4*)(g_Ex + (size_t)r * W_IMG + x0) = ex;
    *(float4*)(g_Ey + (size_t)r * H_IMG + x0) = ey;
}

// ---------------------------------------------------------------------------
// Kernel 2: main contraction (scalar FFMA + premultiplied p).
// Block = (batch, y-tile of 8 rows, n-split). 128 threads, thread = column x.
// ---------------------------------------------------------------------------
__global__ __launch_bounds__(128) void splat_kernel()
{
    int blk = blockIdx.x;
    int ns  = blk % NSPLIT;
    int yt  = (blk / NSPLIT) % NYT;
    int b   = blk / (NSPLIT * NYT);
    int x   = threadIdx.x;
    int y0  = yt * TY;
    int n0  = ns * NPB;

    __shared__ float  sEx[CHUNK * W_IMG];     // 32 KB
    __shared__ float4 sEy[CHUNK * 2];         // 2 KB : 8 ey values per gaussian
    __shared__ float4 sG [CHUNK];             // 1 KB

    float4 acc[TY];
#pragma unroll
    for (int j = 0; j < TY; j++) acc[j] = make_float4(0.f, 0.f, 0.f, 0.f);

    const float* Exb = g_Ex + (size_t)(b*N_G + n0) * W_IMG;
    const float* Eyb = g_Ey + (size_t)(b*N_G + n0) * H_IMG + y0;

    for (int c0 = 0; c0 < NPB; c0 += CHUNK) {
        __syncthreads();
        // Ex chunk: CHUNK*W contiguous floats -> float4 copy
        {
            const float4* src = (const float4*)(Exb + c0 * W_IMG);
            float4* dst = (float4*)sEx;
#pragma unroll
            for (int i = 0; i < (CHUNK * W_IMG / 4) / 128; i++)
                dst[i*128 + x] = src[i*128 + x];
        }
        // Ey chunk: CHUNK rows x TY cols (stride H). 128 float4 = 1 per thread.
        {
            int nl   = x >> 1;
            int half = x & 1;
            sEy[x] = *(const float4*)(Eyb + (c0 + nl) * H_IMG + half * 4);
        }
        // G chunk: CHUNK float4
        if (x < CHUNK) sG[x] = g_G[n0 + c0 + x];
        __syncthreads();

#pragma unroll 4
        for (int nl = 0; nl < CHUNK; nl++) {
            float  ex = sEx[nl * W_IMG + x];
            float4 g  = sG[nl];
            // premultiply: p = ex * g  (4 muls, saves 8 w-muls)
            float px_ = ex * g.x, py_ = ex * g.y, pz_ = ex * g.z, pw_ = ex * g.w;
            float4 eA = sEy[nl*2 + 0];
            float4 eB = sEy[nl*2 + 1];
            float eyv[TY];
            eyv[0] = eA.x; eyv[1] = eA.y; eyv[2] = eA.z; eyv[3] = eA.w;
            eyv[4] = eB.x; eyv[5] = eB.y; eyv[6] = eB.z; eyv[7] = eB.w;
#pragma unroll
            for (int j = 0; j < TY; j++) {
                acc[j].x += px_ * eyv[j];
                acc[j].y += py_ * eyv[j];
                acc[j].z += pz_ * eyv[j];
                acc[j].w += pw_ * eyv[j];
            }
        }
    }

    float4* pp = g_part + (size_t)(ns*BATCH + b) * H_IMG * W_IMG;
#pragma unroll
    for (int j = 0; j < TY; j++)
        pp[(y0 + j) * W_IMG + x] = acc[j];
}

// ---------------------------------------------------------------------------
// Kernel 3: reduce n-splits, normalize, write [B,3,H,W].
// 2 threads per pixel (each sums NSPLIT/2 partials), shfl_xor combine.
// ---------------------------------------------------------------------------
__global__ __launch_bounds__(256) void finalize_kernel(float* __restrict__ out)
{
    int idx = blockIdx.x * blockDim.x + threadIdx.x;   // 0 .. 64K-1
    int pix = idx >> 1;
    int h   = idx & 1;
    int b   = pix / (H_IMG * W_IMG);
    int p   = pix - b * (H_IMG * W_IMG);

    float sx = 0.f, sy = 0.f, sz = 0.f, sw = 0.f;
#pragma unroll
    for (int k = 0; k < NSPLIT/2; k++) {
        int ns = h * (NSPLIT/2) + k;
        float4 v = g_part[(size_t)(ns*BATCH + b) * H_IMG * W_IMG + p];
        sx += v.x; sy += v.y; sz += v.z; sw += v.w;
    }
    sx += __shfl_xor_sync(0xFFFFFFFFu, sx, 1);
    sy += __shfl_xor_sync(0xFFFFFFFFu, sy, 1);
    sz += __shfl_xor_sync(0xFFFFFFFFu, sz, 1);
    sw += __shfl_xor_sync(0xFFFFFFFFu, sw, 1);

    if (h == 0) {
        float invd = 1.0f / (sw + 1e-8f);
        size_t base = (size_t)b * 3 * H_IMG * W_IMG;
        out[base + 0*H_IMG*W_IMG + p] = sx * invd;
        out[base + 1*H_IMG*W_IMG + p] = sy * invd;
        out[base + 2*H_IMG*W_IMG + p] = sz * invd;
    }
}

// ---------------------------------------------------------------------------
extern "C" void kernel_launch(void* const* d_in, const int* in_sizes, int n_in,
                              void* d_out, int out_size)
{
    const float* positions = (const float*)d_in[0];
    const float* colors    = (const float*)d_in[1];
    const float* opacities = (const float*)d_in[2];
    const float* scales    = (const float*)d_in[3];
    const float* qvec      = (const float*)d_in[4];
    const float* tvec      = (const float*)d_in[5];
    float* out = (float*)d_out;

    param_kernel<<<(BATCH * N_G + 255) / 256, 256>>>(positions, colors, opacities, scales, qvec, tvec);
    fill_kernel<<<(BATCH * N_G * W_IMG / 4) / 256, 256>>>();
    splat_kernel<<<BATCH * NYT * NSPLIT, 128>>>();
    finalize_kernel<<<(2 * BATCH * H_IMG * W_IMG) / 256, 256>>>(out);
}

// round 10
// speedup vs baseline: 2.8763x; 1.8163x over previous
#include <cuda_runtime.h>
#include <math.h>

#define N_G   4096
#define BATCH 2
#define HW    128
#define KT    8      // K splits
#define KC    512    // K per CTA
#define NT    8      // N tiles of 64
#define NC    64
#define KCH   64     // K chunk staged in smem

typedef unsigned int u32;

// -------------------- device scratch (no allocation allowed) ---------------
__device__ float4 g_P[BATCH * N_G];                    // px, py, 0.5/var
__device__ float  g_Gf[4 * N_G];                       // [c][n] = op*col (c=3: op)
__device__ float  g_EyT[BATCH * HW * N_G];             // [b][y][n]  4MB (tf32-rounded)
__device__ float  g_ExT[BATCH * HW * N_G];             // [b][x][n]  4MB
__device__ float  g_BT [BATCH * 4 * HW * N_G];         // [b][c*128+x][n] 16MB
__device__ float  g_part[KT * BATCH * HW * 512];       // [kt][b][y][j] 4MB

__device__ __forceinline__ u32 smem_u32(const void* p) {
    u32 a; asm("{ .reg .u64 t; cvta.to.shared.u64 t, %1; cvt.u32.u64 %0, t; }"
               : "=r"(a) : "l"(p)); return a;
}
__device__ __forceinline__ float to_tf32(float x) {
    u32 r; asm("cvt.rna.tf32.f32 %0, %1;" : "=r"(r) : "f"(x));
    return __uint_as_float(r);
}

// ---------------------------------------------------------------------------
// K1: per (b,n) projection params; per-n color table (fp32).
// ---------------------------------------------------------------------------
__global__ __launch_bounds__(256) void param_kernel(
    const float* __restrict__ pos, const float* __restrict__ col,
    const float* __restrict__ opa, const float* __restrict__ sca,
    const float* __restrict__ qv,  const float* __restrict__ tv)
{
    int idx = blockIdx.x * blockDim.x + threadIdx.x;
    if (idx >= BATCH * N_G) return;
    int b = idx / N_G;
    int n = idx - b * N_G;

    float qw = qv[b*4+0], qx = qv[b*4+1], qy = qv[b*4+2], qz = qv[b*4+3];
    float inv = rsqrtf(qw*qw + qx*qx + qy*qy + qz*qz);
    qw *= inv; qx *= inv; qy *= inv; qz *= inv;

    float r00 = 1.f-2.f*(qy*qy+qz*qz), r01 = 2.f*(qx*qy-qz*qw), r02 = 2.f*(qx*qz+qy*qw);
    float r10 = 2.f*(qx*qy+qz*qw), r11 = 1.f-2.f*(qx*qx+qz*qz), r12 = 2.f*(qy*qz-qx*qw);
    float r20 = 2.f*(qx*qz-qy*qw), r21 = 2.f*(qy*qz+qx*qw), r22 = 1.f-2.f*(qx*qx+qy*qy);

    float p0 = pos[n*3+0], p1 = pos[n*3+1], p2 = pos[n*3+2];
    float cx = r00*p0 + r01*p1 + r02*p2 + tv[b*3+0];
    float cy = r10*p0 + r11*p1 + r12*p2 + tv[b*3+1];
    float cz = r20*p0 + r21*p1 + r22*p2 + tv[b*3+2];

    float invz = 1.0f / cz;
    float px = cx * invz * 500.0f + 64.0f;
    float py = cy * invz * 500.0f + 64.0f;
    float s  = sca[n];
    g_P[idx] = make_float4(px, py, 0.5f / (s*s), 0.f);

    if (b == 0) {
        float o = opa[n];
        g_Gf[0*N_G + n] = o * col[n*3+0];
        g_Gf[1*N_G + n] = o * col[n*3+1];
        g_Gf[2*N_G + n] = o * col[n*3+2];
        g_Gf[3*N_G + n] = o;
    }
}

// ---------------------------------------------------------------------------
// K2: transposed exp tables (tf32-rounded fp32).
// warp <-> (tab, b, coordgrp of 8, ngrp of 32); lane <-> n.
// ---------------------------------------------------------------------------
__global__ __launch_bounds__(256) void fillT_kernel()
{
    int wg   = (blockIdx.x * 256 + threadIdx.x) >> 5;
    int lane = threadIdx.x & 31;
    int ngrp = wg & 127;
    int ygrp = (wg >> 7) & 15;
    int b    = (wg >> 11) & 1;
    int tab  = wg >> 12;
    int n    = ngrp * 32 + lane;

    float4 P = g_P[b * N_G + n];
    float ctr = tab ? P.x : P.y;      // tab0 = Ey (py), tab1 = Ex (px)
    float* base = (tab ? g_ExT : g_EyT) + ((size_t)(b*HW + ygrp*8) * N_G) + n;
    float f0 = (float)(ygrp * 8) - ctr;
#pragma unroll
    for (int j = 0; j < 8; j++) {
        float d = f0 + (float)j;
        base[(size_t)j * N_G] = to_tf32(__expf(-d*d*P.z));
    }
}

// ---------------------------------------------------------------------------
// K3: BT[b][c*128+x][n] = ExT[b][x][n] * Gf[c][n]  (tf32-rounded fp32).
// ---------------------------------------------------------------------------
__global__ __launch_bounds__(256) void bfill_kernel()
{
    __shared__ float sG[4][256];
    int blk = blockIdx.x;
    int nchunk = blk & 15;
    int xg     = (blk >> 4) & 15;
    int b      = blk >> 8;
    int t  = threadIdx.x;
    int n0 = nchunk * 256;

#pragma unroll
    for (int c = 0; c < 4; c++) sG[c][t] = g_Gf[c*N_G + n0 + t];
    __syncthreads();

#pragma unroll
    for (int xx = 0; xx < 8; xx++) {
        int x = xg * 8 + xx;
        float ex = g_ExT[((size_t)(b*HW + x)) * N_G + n0 + t];
#pragma unroll
        for (int c = 0; c < 4; c++) {
            g_BT[((size_t)(b*512 + c*HW + x)) * N_G + n0 + t] = to_tf32(ex * sG[c][t]);
        }
    }
}

// ---------------------------------------------------------------------------
// K4: tf32 MMA GEMM  D[128(y) x 64(j)] = A[128 x 512] . B[64 x 512]^T
// grid = 128: blk -> kt(8) x nt(8) x b(2). 128 threads = 4 warps.
// K chunks of 64 double-buffered via cp.async; XOR-granule swizzle;
// per-thread LDS.32 fragment loads per the PTX m16n8k8 tf32 fragment tables.
// ---------------------------------------------------------------------------
#define ABUF 8192              // floats per A buffer (128 x 64)
#define BOFF 16384             // float offset of B region
#define BBUF 4096              // floats per B buffer (64 x 64)
#define GEMM_SMEM ((BOFF + 2 * BBUF) * 4)   // 96 KB

__global__ __launch_bounds__(128) void gemm_kernel()
{
    extern __shared__ float smem[];
    int tid = threadIdx.x, w = tid >> 5, lane = tid & 31;
    int blk = blockIdx.x;
    int kt = blk & 7, nt = (blk >> 3) & 7, b = blk >> 6;

    const float* Asrc = g_EyT + (size_t)b * HW * N_G + kt * KC;
    const float* Bsrc = g_BT + ((size_t)(b * 512 + nt * NC)) * N_G + kt * KC;
    u32 sbase = smem_u32(smem);

    float acc[2][8][4];
#pragma unroll
    for (int mt = 0; mt < 2; mt++)
#pragma unroll
        for (int nn = 0; nn < 8; nn++)
#pragma unroll
            for (int r = 0; r < 4; r++) acc[mt][nn][r] = 0.f;

    auto issue = [&](int ch, int buf) {
        // A: 128 rows x 16 granules of 4 floats
#pragma unroll
        for (int i = 0; i < 16; i++) {
            int id = i * 128 + tid;
            int row = id >> 4, g4 = id & 15;
            const float* src = Asrc + (size_t)row * N_G + ch * KCH + g4 * 4;
            u32 dst = sbase + (u32)(buf * ABUF + row * 64 + ((g4 ^ (row & 7)) << 2)) * 4;
            asm volatile("cp.async.cg.shared.global [%0], [%1], 16;" :: "r"(dst), "l"(src));
        }
        // B: 64 rows x 16 granules
#pragma unroll
        for (int i = 0; i < 8; i++) {
            int id = i * 128 + tid;
            int row = id >> 4, g4 = id & 15;
            const float* src = Bsrc + (size_t)row * N_G + ch * KCH + g4 * 4;
            u32 dst = sbase + (u32)(BOFF + buf * BBUF + row * 64 + ((g4 ^ (row & 7)) << 2)) * 4;
            asm volatile("cp.async.cg.shared.global [%0], [%1], 16;" :: "r"(dst), "l"(src));
        }
        asm volatile("cp.async.commit_group;" ::: "memory");
    };

    int r0 = (lane >> 2);   // 0..7  (group id)
    int quad = lane & 3;    // 0..3  (thread in group)

    issue(0, 0);
    for (int ch = 0; ch < 8; ch++) {
        if (ch < 7) {
            issue(ch + 1, (ch + 1) & 1);
            asm volatile("cp.async.wait_group 1;" ::: "memory");
        } else {
            asm volatile("cp.async.wait_group 0;" ::: "memory");
        }
        __syncthreads();

        const u32* A = (const u32*)(smem + (ch & 1) * ABUF);
        const u32* B = (const u32*)(smem + BOFF + (ch & 1) * BBUF);

#pragma unroll
        for (int ks = 0; ks < 8; ks++) {
            int g0 = 2 * ks, g1 = 2 * ks + 1;
            u32 a[2][4];
#pragma unroll
            for (int mt = 0; mt < 2; mt++) {
                int row = w * 32 + mt * 16 + r0;        // row&7 == r0
                int base0 = row * 64 + quad;
                a[mt][0] = A[base0 + ((g0 ^ r0) << 2)];
                a[mt][1] = A[base0 + 512 + ((g0 ^ r0) << 2)];
                a[mt][2] = A[base0 + ((g1 ^ r0) << 2)];
                a[mt][3] = A[base0 + 512 + ((g1 ^ r0) << 2)];
            }
#pragma unroll
            for (int nn = 0; nn < 8; nn++) {
                int n = nn * 8 + r0;                    // n&7 == r0
                int nb = n * 64 + quad;
                u32 b0 = B[nb + ((g0 ^ r0) << 2)];
                u32 b1 = B[nb + ((g1 ^ r0) << 2)];
#pragma unroll
                for (int mt = 0; mt < 2; mt++) {
                    asm volatile(
                        "mma.sync.aligned.m16n8k8.row.col.f32.tf32.tf32.f32 "
                        "{%0,%1,%2,%3}, {%4,%5,%6,%7}, {%8,%9}, {%0,%1,%2,%3};"
                        : "+f"(acc[mt][nn][0]), "+f"(acc[mt][nn][1]),
                          "+f"(acc[mt][nn][2]), "+f"(acc[mt][nn][3])
                        : "r"(a[mt][0]), "r"(a[mt][1]), "r"(a[mt][2]), "r"(a[mt][3]),
                          "r"(b0), "r"(b1));
                }
            }
        }
        __syncthreads();
    }

    // epilogue: partial [kt][b][y][j], float2 stores
    float* pp = g_part + ((size_t)(kt * BATCH + b) * HW) * 512;
#pragma unroll
    for (int mt = 0; mt < 2; mt++) {
        int y0 = w * 32 + mt * 16 + r0;
        int jb = quad * 2;
#pragma unroll
        for (int nn = 0; nn < 8; nn++) {
            int j = nt * NC + nn * 8 + jb;
            *(float2*)&pp[(size_t)y0 * 512 + j]       = make_float2(acc[mt][nn][0], acc[mt][nn][1]);
            *(float2*)&pp[(size_t)(y0 + 8) * 512 + j] = make_float2(acc[mt][nn][2], acc[mt][nn][3]);
        }
    }
}

// ---------------------------------------------------------------------------
// K5: sum 8 K-split partials, normalize, write [B,3,H,W].
// 2 threads per pixel (split kt), shfl_xor combine.
// ---------------------------------------------------------------------------
__global__ __launch_bounds__(256) void finalize_kernel(float* __restrict__ out)
{
    int idx = blockIdx.x * 256 + threadIdx.x;   // 0..65535
    int h = idx & 1;
    int x = (idx >> 1) & 127;
    int y = (idx >> 8) & 127;
    int b = idx >> 15;

    float s0 = 0.f, s1 = 0.f, s2 = 0.f, s3 = 0.f;
#pragma unroll
    for (int k = 0; k < KT/2; k++) {
        int kt = h * (KT/2) + k;
        const float* base = g_part + ((size_t)(kt * BATCH + b) * HW + y) * 512;
        s0 += base[0*HW + x];
        s1 += base[1*HW + x];
        s2 += base[2*HW + x];
        s3 += base[3*HW + x];
    }
    s0 += __shfl_xor_sync(0xFFFFFFFFu, s0, 1);
    s1 += __shfl_xor_sync(0xFFFFFFFFu, s1, 1);
    s2 += __shfl_xor_sync(0xFFFFFFFFu, s2, 1);
    s3 += __shfl_xor_sync(0xFFFFFFFFu, s3, 1);

    if (h == 0) {
        float invd = 1.0f / (s3 + 1e-8f);
        size_t o = ((size_t)(b * 3) * HW + y) * HW + x;
        out[o]            = s0 * invd;
        out[o + HW*HW]    = s1 * invd;
        out[o + 2*HW*HW]  = s2 * invd;
    }
}

// ---------------------------------------------------------------------------
extern "C" void kernel_launch(void* const* d_in, const int* in_sizes, int n_in,
                              void* d_out, int out_size)
{
    const float* positions = (const float*)d_in[0];
    const float* colors    = (const float*)d_in[1];
    const float* opacities = (const float*)d_in[2];
    const float* scales    = (const float*)d_in[3];
    const float* qvec      = (const float*)d_in[4];
    const float* tvec      = (const float*)d_in[5];
    float* out = (float*)d_out;

    cudaFuncSetAttribute(gemm_kernel, cudaFuncAttributeMaxDynamicSharedMemorySize, GEMM_SMEM);

    param_kernel<<<(BATCH * N_G + 255) / 256, 256>>>(positions, colors, opacities, scales, qvec, tvec);
    fillT_kernel<<<1024, 256>>>();
    bfill_kernel<<<512, 256>>>();
    gemm_kernel<<<BATCH * NT * KT, 128, GEMM_SMEM>>>();
    finalize_kernel<<<(2 * BATCH * HW * HW) / 256, 256>>>(out);
}

// round 16
// speedup vs baseline: 3.4427x; 1.1969x over previous
#include <cuda_runtime.h>
#include <math.h>

#define N_G   4096
#define BATCH 2
#define HW    128
#define KT    16     // K splits
#define KC    256    // K per CTA
#define NT    8      // N tiles of 64
#define NC    64
#define KCH   64     // K chunk staged in smem

typedef unsigned int u32;

// -------------------- device scratch (no allocation allowed) ---------------
__device__ float4 g_P[BATCH * N_G];                    // px, py, 0.5/var
__device__ float  g_Gf[4 * N_G];                       // [c][n] = op*col (c=3: op)
__device__ float  g_EyT[BATCH * HW * N_G];             // [b][y][n]  4MB (tf32-rounded)
__device__ float  g_ExT[BATCH * HW * N_G];             // [b][x][n]  4MB
__device__ float  g_part[KT * BATCH * HW * 512];       // [kt][b][y][j] 8MB

__device__ __forceinline__ u32 smem_u32(const void* p) {
    u32 a; asm("{ .reg .u64 t; cvta.to.shared.u64 t, %1; cvt.u32.u64 %0, t; }"
               : "=r"(a) : "l"(p)); return a;
}
__device__ __forceinline__ float to_tf32(float x) {
    u32 r; asm("cvt.rna.tf32.f32 %0, %1;" : "=r"(r) : "f"(x));
    return __uint_as_float(r);
}

// ---------------------------------------------------------------------------
// K1: per (b,n) projection params; per-n color table (fp32).
// ---------------------------------------------------------------------------
__global__ __launch_bounds__(256) void param_kernel(
    const float* __restrict__ pos, const float* __restrict__ col,
    const float* __restrict__ opa, const float* __restrict__ sca,
    const float* __restrict__ qv,  const float* __restrict__ tv)
{
    int idx = blockIdx.x * blockDim.x + threadIdx.x;
    if (idx >= BATCH * N_G) return;
    int b = idx / N_G;
    int n = idx - b * N_G;

    float qw = qv[b*4+0], qx = qv[b*4+1], qy = qv[b*4+2], qz = qv[b*4+3];
    float inv = rsqrtf(qw*qw + qx*qx + qy*qy + qz*qz);
    qw *= inv; qx *= inv; qy *= inv; qz *= inv;

    float r00 = 1.f-2.f*(qy*qy+qz*qz), r01 = 2.f*(qx*qy-qz*qw), r02 = 2.f*(qx*qz+qy*qw);
    float r10 = 2.f*(qx*qy+qz*qw), r11 = 1.f-2.f*(qx*qx+qz*qz), r12 = 2.f*(qy*qz-qx*qw);
    float r20 = 2.f*(qx*qz-qy*qw), r21 = 2.f*(qy*qz+qx*qw), r22 = 1.f-2.f*(qx*qx+qy*qy);

    float p0 = pos[n*3+0], p1 = pos[n*3+1], p2 = pos[n*3+2];
    float cx = r00*p0 + r01*p1 + r02*p2 + tv[b*3+0];
    float cy = r10*p0 + r11*p1 + r12*p2 + tv[b*3+1];
    float cz = r20*p0 + r21*p1 + r22*p2 + tv[b*3+2];

    float invz = 1.0f / cz;
    float px = cx * invz * 500.0f + 64.0f;
    float py = cy * invz * 500.0f + 64.0f;
    float s  = sca[n];
    g_P[idx] = make_float4(px, py, 0.5f / (s*s), 0.f);

    if (b == 0) {
        float o = opa[n];
        g_Gf[0*N_G + n] = o * col[n*3+0];
        g_Gf[1*N_G + n] = o * col[n*3+1];
        g_Gf[2*N_G + n] = o * col[n*3+2];
        g_Gf[3*N_G + n] = o;
    }
}

// ---------------------------------------------------------------------------
// K2: transposed exp tables (tf32-rounded fp32).
// ---------------------------------------------------------------------------
__global__ __launch_bounds__(256) void fillT_kernel()
{
    int wg   = (blockIdx.x * 256 + threadIdx.x) >> 5;
    int lane = threadIdx.x & 31;
    int ngrp = wg & 127;
    int ygrp = (wg >> 7) & 15;
    int b    = (wg >> 11) & 1;
    int tab  = wg >> 12;
    int n    = ngrp * 32 + lane;

    float4 P = g_P[b * N_G + n];
    float ctr = tab ? P.x : P.y;      // tab0 = Ey (py), tab1 = Ex (px)
    float* base = (tab ? g_ExT : g_EyT) + ((size_t)(b*HW + ygrp*8) * N_G) + n;
    float f0 = (float)(ygrp * 8) - ctr;
#pragma unroll
    for (int j = 0; j < 8; j++) {
        float d = f0 + (float)j;
        base[(size_t)j * N_G] = to_tf32(__expf(-d*d*P.z));
    }
}

// ---------------------------------------------------------------------------
// K3: tf32 MMA GEMM  D[128(y) x 64(j)] = A[128 x 256] . B[64 x 256]^T
// grid = 256: blk -> kt(16) x nt(8) x b(2). 128 threads = 4 warps, 2 CTA/SM.
// A via cp.async double-buffer; B scaled on the fly (Ex * g_c) with register
// prefetch overlap. XOR-granule swizzle; per-thread LDS fragment loads.
// ---------------------------------------------------------------------------
#define ABUF 8192              // floats per A buffer (128 x 64)
#define BOFF 16384             // float offset of B region
#define BBUF 4096              // floats per B buffer (64 x 64)
#define GEMM_SMEM ((BOFF + 2 * BBUF) * 4)   // 96 KB
#define NCHUNK (KC / KCH)      // 4

__global__ __launch_bounds__(128, 2) void gemm_kernel()
{
    extern __shared__ float smem[];
    int tid = threadIdx.x, w = tid >> 5, lane = tid & 31;
    int blk = blockIdx.x;
    int kt = blk & 15, nt = (blk >> 4) & 7, b = blk >> 7;
    int c  = nt >> 1;              // color channel of this j-tile
    int x0 = (nt & 1) * 64;        // x range of this j-tile

    const float* Asrc = g_EyT + (size_t)b * HW * N_G + kt * KC;
    const float* Bsrc = g_ExT + ((size_t)(b * HW + x0)) * N_G + kt * KC;
    const float* Gsrc = g_Gf + (size_t)c * N_G + kt * KC;
    u32 sbase = smem_u32(smem);

    int ldrow = tid >> 4;          // 0..7   (B-load row group base)
    int ldg4  = tid & 15;          // granule

    float acc[2][8][4];
#pragma unroll
    for (int mt = 0; mt < 2; mt++)
#pragma unroll
        for (int nn = 0; nn < 8; nn++)
#pragma unroll
            for (int r = 0; r < 4; r++) acc[mt][nn][r] = 0.f;

    auto issueA = [&](int ch, int buf) {
#pragma unroll
        for (int i = 0; i < 16; i++) {
            int id = i * 128 + tid;
            int row = id >> 4, g4 = id & 15;
            const float* src = Asrc + (size_t)row * N_G + ch * KCH + g4 * 4;
            u32 dst = sbase + (u32)(buf * ABUF + row * 64 + ((g4 ^ (row & 7)) << 2)) * 4;
            asm volatile("cp.async.cg.shared.global [%0], [%1], 16;" :: "r"(dst), "l"(src));
        }
        asm volatile("cp.async.commit_group;" ::: "memory");
    };

    float4 vB[8];
    auto loadB = [&](int ch) {
        const float4 gv = *(const float4*)(Gsrc + ch * KCH + ldg4 * 4);
#pragma unroll
        for (int i = 0; i < 8; i++) {
            int row = i * 8 + ldrow;           // 0..63
            const float4 v  = *(const float4*)(Bsrc + (size_t)row * N_G + ch * KCH + ldg4 * 4);
            vB[i].x = to_tf32(v.x * gv.x);
            vB[i].y = to_tf32(v.y * gv.y);
            vB[i].z = to_tf32(v.z * gv.z);
            vB[i].w = to_tf32(v.w * gv.w);
        }
    };
    auto stsB = [&](int buf) {
#pragma unroll
        for (int i = 0; i < 8; i++) {
            int row = i * 8 + ldrow;
            *(float4*)(smem + BOFF + buf * BBUF + row * 64 + ((ldg4 ^ (row & 7)) << 2)) = vB[i];
        }
    };

    int r0 = (lane >> 2);   // 0..7
    int quad = lane & 3;    // 0..3

    loadB(0);
    issueA(0, 0);
    for (int ch = 0; ch < NCHUNK; ch++) {
        stsB(ch & 1);
        if (ch < NCHUNK - 1) {
            loadB(ch + 1);
            issueA(ch + 1, (ch + 1) & 1);
            asm volatile("cp.async.wait_group 1;" ::: "memory");
        } else {
            asm volatile("cp.async.wait_group 0;" ::: "memory");
        }
        __syncthreads();

        const u32* A = (const u32*)(smem + (ch & 1) * ABUF);
        const u32* B = (const u32*)(smem + BOFF + (ch & 1) * BBUF);

#pragma unroll
        for (int ks = 0; ks < 8; ks++) {
            int g0 = 2 * ks, g1 = 2 * ks + 1;
            u32 a[2][4];
#pragma unroll
            for (int mt = 0; mt < 2; mt++) {
                int row = w * 32 + mt * 16 + r0;
                int base0 = row * 64 + quad;
                a[mt][0] = A[base0 + ((g0 ^ r0) << 2)];
                a[mt][1] = A[base0 + 512 + ((g0 ^ r0) << 2)];
                a[mt][2] = A[base0 + ((g1 ^ r0) << 2)];
                a[mt][3] = A[base0 + 512 + ((g1 ^ r0) << 2)];
            }
#pragma unroll
            for (int nn = 0; nn < 8; nn++) {
                int n = nn * 8 + r0;
                int nb = n * 64 + quad;
                u32 b0 = B[nb + ((g0 ^ r0) << 2)];
                u32 b1 = B[nb + ((g1 ^ r0) << 2)];
#pragma unroll
                for (int mt = 0; mt < 2; mt++) {
                    asm volatile(
                        "mma.sync.aligned.m16n8k8.row.col.f32.tf32.tf32.f32 "
                        "{%0,%1,%2,%3}, {%4,%5,%6,%7}, {%8,%9}, {%0,%1,%2,%3};"
                        : "+f"(acc[mt][nn][0]), "+f"(acc[mt][nn][1]),
                          "+f"(acc[mt][nn][2]), "+f"(acc[mt][nn][3])
                        : "r"(a[mt][0]), "r"(a[mt][1]), "r"(a[mt][2]), "r"(a[mt][3]),
                          "r"(b0), "r"(b1));
                }
            }
        }
        __syncthreads();
    }

    // epilogue: partial [kt][b][y][j], float2 stores
    float* pp = g_part + ((size_t)(kt * BATCH + b) * HW) * 512;
#pragma unroll
    for (int mt = 0; mt < 2; mt++) {
        int y0 = w * 32 + mt * 16 + r0;
        int jb = quad * 2;
#pragma unroll
        for (int nn = 0; nn < 8; nn++) {
            int j = nt * NC + nn * 8 + jb;
            *(float2*)&pp[(size_t)y0 * 512 + j]       = make_float2(acc[mt][nn][0], acc[mt][nn][1]);
            *(float2*)&pp[(size_t)(y0 + 8) * 512 + j] = make_float2(acc[mt][nn][2], acc[mt][nn][3]);
        }
    }
}

// ---------------------------------------------------------------------------
// K4: sum 16 K-split partials, normalize, write [B,3,H,W].
// 4 threads per pixel (each sums 4 kt), 2-level shfl_xor combine.
// ---------------------------------------------------------------------------
__global__ __launch_bounds__(256) void finalize_kernel(float* __restrict__ out)
{
    int idx = blockIdx.x * 256 + threadIdx.x;   // 0..131071
    int h = idx & 3;
    int x = (idx >> 2) & 127;
    int y = (idx >> 9) & 127;
    int b = idx >> 16;

    float s0 = 0.f, s1 = 0.f, s2 = 0.f, s3 = 0.f;
#pragma unroll
    for (int k = 0; k < KT/4; k++) {
        int kt = h * (KT/4) + k;
        const float* base = g_part + ((size_t)(kt * BATCH + b) * HW + y) * 512;
        s0 += base[0*HW + x];
        s1 += base[1*HW + x];
        s2 += base[2*HW + x];
        s3 += base[3*HW + x];
    }
#pragma unroll
    for (int d = 1; d <= 2; d <<= 1) {
        s0 += __shfl_xor_sync(0xFFFFFFFFu, s0, d);
        s1 += __shfl_xor_sync(0xFFFFFFFFu, s1, d);
        s2 += __shfl_xor_sync(0xFFFFFFFFu, s2, d);
        s3 += __shfl_xor_sync(0xFFFFFFFFu, s3, d);
    }

    if (h == 0) {
        float invd = 1.0f / (s3 + 1e-8f);
        size_t o = ((size_t)(b * 3) * HW + y) * HW + x;
        out[o]            = s0 * invd;
        out[o + HW*HW]    = s1 * invd;
        out[o + 2*HW*HW]  = s2 * invd;
    }
}

// ---------------------------------------------------------------------------
extern "C" void kernel_launch(void* const* d_in, const int* in_sizes, int n_in,
                              void* d_out, int out_size)
{
    const float* positions = (const float*)d_in[0];
    const float* colors    = (const float*)d_in[1];
    const float* opacities = (const float*)d_in[2];
    const float* scales    = (const float*)d_in[3];
    const float* qvec      = (const float*)d_in[4];
    const float* tvec      = (const float*)d_in[5];
    float* out = (float*)d_out;

    cudaFuncSetAttribute(gemm_kernel, cudaFuncAttributeMaxDynamicSharedMemorySize, GEMM_SMEM);

    param_kernel<<<(BATCH * N_G + 255) / 256, 256>>>(positions, colors, opacities, scales, qvec, tvec);
    fillT_kernel<<<1024, 256>>>();
    gemm_kernel<<<BATCH * NT * KT, 128, GEMM_SMEM>>>();
    finalize_kernel<<<(4 * BATCH * HW * HW) / 256, 256>>>(out);
}